// round 7
// baseline (speedup 1.0000x reference)
#include <cuda_runtime.h>
#include <cuda_bf16.h>
#include <math.h>
#include <stdint.h>

// Problem dims (fixed by the dataset)
constexpr int Nn  = 4000;
constexpr int Ee  = 50000;
constexpr int NGg = 12;
constexpr int Hh  = 128;
constexpr int BDd = 128;
constexpr int Ll  = 2;
constexpr int Bb  = 100;

constexpr int EROWS = Ee * NGg;     // 600000
constexpr int NROWS = Nn * NGg;     // 48000

// ---------------- scratch (device globals; no cudaMalloc allowed) -------------
__device__ __align__(16) float g_grid_node[Nn * NGg * 3];
__device__ __align__(16) float g_eipoly[EROWS * 12];
__device__ __align__(16) float g_bufA[EROWS * BDd];      // h1 (basis MLP hidden)
__device__ __align__(16) float g_basis[EROWS * BDd];
__device__ __align__(16) float g_x  [NROWS * Hh];
__device__ __align__(16) float g_x1 [NROWS * Hh];
__device__ __align__(16) float g_x2 [NROWS * Hh];
__device__ __align__(16) float g_ffh[NROWS * 4 * Hh];
__device__ __align__(16) float g_fipoly[NGg * NGg * 2];
__device__ __align__(16) float g_fh1   [NGg * NGg * Hh];
__device__ __align__(16) float g_fbasis[NGg * NGg * BDd];
__device__ __align__(16) float g_fk    [NGg * NGg * Hh];
__device__ float g_gsum[Bb * 4];   // per-graph: sum_x, sum_y, sum_z, count

__device__ __forceinline__ float gelu_f(float x) {
    return 0.5f * x * (1.0f + erff(x * 0.70710678118654752f));
}

// ---------------- tiny kernels -------------------------------------------------
__global__ void k_zero(float* p, int n) {
    int i = blockIdx.x * blockDim.x + threadIdx.x;
    if (i < n) p[i] = 0.f;
}

__global__ void k_gsum(const float* __restrict__ pos, const int* __restrict__ batch) {
    int n = blockIdx.x * blockDim.x + threadIdx.x;
    if (n >= Nn) return;
    int b = batch[n];
    atomicAdd(&g_gsum[b * 4 + 0], pos[n * 3 + 0]);
    atomicAdd(&g_gsum[b * 4 + 1], pos[n * 3 + 1]);
    atomicAdd(&g_gsum[b * 4 + 2], pos[n * 3 + 2]);
    atomicAdd(&g_gsum[b * 4 + 3], 1.f);
}

__global__ void k_grid_node(const int* __restrict__ batch,
                            const float* __restrict__ grid0,
                            const float* __restrict__ R) {
    int idx = blockIdx.x * blockDim.x + threadIdx.x;  // n*NG + k
    if (idx >= Nn * NGg) return;
    int n = idx / NGg, k = idx % NGg;
    const float* Rb = R + batch[n] * 9;
    float gx = grid0[k * 3 + 0], gy = grid0[k * 3 + 1], gz = grid0[k * 3 + 2];
    float* o = g_grid_node + idx * 3;
    o[0] = Rb[0] * gx + Rb[1] * gy + Rb[2] * gz;
    o[1] = Rb[3] * gx + Rb[4] * gy + Rb[5] * gz;
    o[2] = Rb[6] * gx + Rb[7] * gy + Rb[8] * gz;
}

__global__ void k_eipoly(const float* __restrict__ pos,
                         const float* __restrict__ charges,
                         const int* __restrict__ eidx) {
    int idx = blockIdx.x * blockDim.x + threadIdx.x;  // e*NG + k
    if (idx >= EROWS) return;
    int e = idx / NGg, k = idx % NGg;
    int s = eidx[e], d = eidx[Ee + e];
    float rx = pos[s * 3 + 0] - pos[d * 3 + 0];
    float ry = pos[s * 3 + 1] - pos[d * 3 + 1];
    float rz = pos[s * 3 + 2] - pos[d * 3 + 2];
    const float* g = g_grid_node + (s * NGg + k) * 3;
    float inv1 = rx * g[0] + ry * g[1] + rz * g[2];
    float vx = rx - inv1 * g[0], vy = ry - inv1 * g[1], vz = rz - inv1 * g[2];
    float inv2 = sqrtf(vx * vx + vy * vy + vz * vz);
    float cp = charges[s] * charges[d];
    float e0 = inv1, e1 = inv2, e2 = cp;
    float* o = g_eipoly + (size_t)idx * 12;
    o[0] = e0;  o[1] = e1;  o[2] = e2;
    o[3] = e0 * e0; o[4]  = e0 * e1; o[5]  = e0 * e2;
    o[6] = e1 * e0; o[7]  = e1 * e1; o[8]  = e1 * e2;
    o[9] = e2 * e0; o[10] = e2 * e1; o[11] = e2 * e2;
}

__global__ void k_fipoly(const float* __restrict__ grid0) {
    int idx = threadIdx.x;
    if (idx >= NGg * NGg) return;
    int p = idx / NGg, o = idx % NGg;
    float fi = grid0[p * 3 + 0] * grid0[o * 3 + 0] +
               grid0[p * 3 + 1] * grid0[o * 3 + 1] +
               grid0[p * 3 + 2] * grid0[o * 3 + 2];
    g_fipoly[idx * 2 + 0] = fi;
    g_fipoly[idx * 2 + 1] = fi * fi;
}

// naive GEMM for tiny fiber matrices (M=144) — fp32, negligible time
__global__ void k_small_gemm(const float* __restrict__ A, const float* __restrict__ W,
                             const float* __restrict__ bias, float* __restrict__ C,
                             int M, int N, int K, int act) {
    int idx = blockIdx.x * blockDim.x + threadIdx.x;
    if (idx >= M * N) return;
    int r = idx / N, c = idx % N;
    float acc = bias ? bias[c] : 0.f;
    for (int k = 0; k < K; k++) acc = fmaf(A[r * K + k], W[k * N + c], acc);
    C[idx] = act ? gelu_f(acc) : acc;
}

__global__ void k_embed(const float* __restrict__ pos, const float* __restrict__ vel,
                        const float* __restrict__ charges, const int* __restrict__ batch,
                        const float* __restrict__ We) {
    int nk = blockIdx.x;           // n*NG + k
    int h = threadIdx.x;           // 0..127
    int n = nk / NGg;
    const float* g = g_grid_node + nk * 3;
    float vx = vel[n * 3 + 0], vy = vel[n * 3 + 1], vz = vel[n * 3 + 2];
    int b = batch[n];
    float cnt = fmaxf(g_gsum[b * 4 + 3], 1.f);
    float rpx = pos[n * 3 + 0] - g_gsum[b * 4 + 0] / cnt;
    float rpy = pos[n * 3 + 1] - g_gsum[b * 4 + 1] / cnt;
    float rpz = pos[n * 3 + 2] - g_gsum[b * 4 + 2] / cnt;
    float f0 = vx * g[0] + vy * g[1] + vz * g[2];
    float f1 = rpx * g[0] + rpy * g[1] + rpz * g[2];
    float f2 = charges[n];
    float f3 = sqrtf(vx * vx + vy * vy + vz * vz);
    g_x[(size_t)nk * Hh + h] =
        f0 * We[h] + f1 * We[Hh + h] + f2 * We[2 * Hh + h] + f3 * We[3 * Hh + h];
}

// x2[n,p,c] = (1/NG) sum_o x1[n,o,c]*fk[p,o,c] + b_conv[c]; then LayerNorm over c
__global__ void k_fiber_ln(const float* __restrict__ bconv, const float* __restrict__ gamma,
                           const float* __restrict__ beta) {
    int np = blockIdx.x;           // n*NG + p
    int n = np / NGg, p = np % NGg;
    int c = threadIdx.x;
    float acc = 0.f;
#pragma unroll
    for (int o = 0; o < NGg; o++)
        acc = fmaf(g_x1[((size_t)(n * NGg + o)) * Hh + c],
                   g_fk[((size_t)(p * NGg + o)) * Hh + c], acc);
    float v = acc * (1.0f / NGg) + bconv[c];

    __shared__ float red[4];
    float s = v;
#pragma unroll
    for (int off = 16; off > 0; off >>= 1) s += __shfl_down_sync(0xffffffffu, s, off);
    if ((c & 31) == 0) red[c >> 5] = s;
    __syncthreads();
    float mean = (red[0] + red[1] + red[2] + red[3]) * (1.f / Hh);
    __syncthreads();
    float dd = v - mean;
    s = dd * dd;
#pragma unroll
    for (int off = 16; off > 0; off >>= 1) s += __shfl_down_sync(0xffffffffu, s, off);
    if ((c & 31) == 0) red[c >> 5] = s;
    __syncthreads();
    float var = (red[0] + red[1] + red[2] + red[3]) * (1.f / Hh);
    g_x2[(size_t)np * Hh + c] = dd * rsqrtf(var + 1e-5f) * gamma[c] + beta[c];
}

// out[n,d] = (1/NG) sum_k grid_node[n,k,d] * (t[n,k,:]·W_ro2 + b_ro2)
__global__ void k_output(const float* __restrict__ Wro2, const float* __restrict__ bro2,
                         float* __restrict__ out) {
    int n = blockIdx.x;
    int h = threadIdx.x;
    __shared__ float red[4];
    __shared__ float ybc;
    float a0 = 0.f, a1 = 0.f, a2 = 0.f;
    for (int k = 0; k < NGg; k++) {
        float s = g_ffh[((size_t)(n * NGg + k)) * Hh + h] * Wro2[h];
#pragma unroll
        for (int off = 16; off > 0; off >>= 1) s += __shfl_down_sync(0xffffffffu, s, off);
        if ((h & 31) == 0) red[h >> 5] = s;
        __syncthreads();
        if (h == 0) ybc = red[0] + red[1] + red[2] + red[3] + bro2[0];
        __syncthreads();
        float y = ybc;
        a0 += g_grid_node[(n * NGg + k) * 3 + 0] * y;
        a1 += g_grid_node[(n * NGg + k) * 3 + 1] * y;
        a2 += g_grid_node[(n * NGg + k) * 3 + 2] * y;
        __syncthreads();
    }
    if (h == 0) {
        out[n * 3 + 0] = a0 * (1.f / NGg);
        out[n * 3 + 1] = a1 * (1.f / NGg);
        out[n * 3 + 2] = a2 * (1.f / NGg);
    }
}

// ---------------- bf16x3 tensor-core GEMM (≈fp32 accuracy) ---------------------
// C = [act](A @ Bw + bias) [+= if ACCUM]
// SCATTER mode (message-passing fusion): instead of storing C, the epilogue does
//   row = e*12+k ; x1[(dst(e)*12+k)*128+c] += C[row][c] * x[(src(e)*12+k)*128+c]
// A: MxK row-major (K % 4 == 0), Bw: KxN row-major, N % 128 == 0.
// Block 128x128, BK=32, 8 warps, warp tile 64x32 via mma.m16n8k16.bf16.
// Split x = hi + lo (hi = bf16(x), lo = bf16(x - hi)); D += hh + hl + lh.
constexpr int BM = 128, BN = 128, BK = 32;
constexpr int ASTRIDE = BK + 8;      // 40 bf16 = 20 u32 per row -> conflict-free ldmatrix
constexpr int BSTRIDE = BN + 8;      // 136 bf16 = 68 u32 per row -> conflict-free ldmatrix.trans

__device__ __forceinline__ void mma_bf16(float* d, const uint32_t* a, const uint32_t* b) {
    asm volatile(
        "mma.sync.aligned.m16n8k16.row.col.f32.bf16.bf16.f32 "
        "{%0,%1,%2,%3}, {%4,%5,%6,%7}, {%8,%9}, {%0,%1,%2,%3};\n"
        : "+f"(d[0]), "+f"(d[1]), "+f"(d[2]), "+f"(d[3])
        : "r"(a[0]), "r"(a[1]), "r"(a[2]), "r"(a[3]), "r"(b[0]), "r"(b[1]));
}

__device__ __forceinline__ void ldm_x4(uint32_t* r, const __nv_bfloat16* p) {
    uint32_t addr = (uint32_t)__cvta_generic_to_shared(p);
    asm volatile("ldmatrix.sync.aligned.m8n8.x4.shared.b16 {%0,%1,%2,%3}, [%4];"
                 : "=r"(r[0]), "=r"(r[1]), "=r"(r[2]), "=r"(r[3]) : "r"(addr));
}

__device__ __forceinline__ void ldm_x2t(uint32_t* r, const __nv_bfloat16* p) {
    uint32_t addr = (uint32_t)__cvta_generic_to_shared(p);
    asm volatile("ldmatrix.sync.aligned.m8n8.x2.trans.shared.b16 {%0,%1}, [%2];"
                 : "=r"(r[0]), "=r"(r[1]) : "r"(addr));
}

__device__ __forceinline__ void split_bf16(float v, __nv_bfloat16& hi, __nv_bfloat16& lo) {
    hi = __float2bfloat16_rn(v);
    lo = __float2bfloat16_rn(v - __bfloat162float(hi));
}

template <bool GELU, bool ACCUM, bool SCATTER>
__global__ void __launch_bounds__(256, 2) gemm_bf16x3(
    const float* __restrict__ A, const float* __restrict__ Bw,
    const float* __restrict__ bias, float* __restrict__ C,
    int M, int N, int K,
    const int* __restrict__ eidx, const float* __restrict__ Xsrc,
    float* __restrict__ X1) {
    __shared__ __nv_bfloat16 As1[BM][ASTRIDE];   // A hi
    __shared__ __nv_bfloat16 As2[BM][ASTRIDE];   // A lo
    __shared__ __nv_bfloat16 Bs1[BK][BSTRIDE];   // B hi (layout [k][n])
    __shared__ __nv_bfloat16 Bs2[BK][BSTRIDE];   // B lo

    const int tid  = threadIdx.x;
    const int lane = tid & 31;
    const int warp = tid >> 5;
    const int wm = warp & 1;             // 2 warps along M (64 rows each)
    const int wn = warp >> 1;            // 4 warps along N (32 cols each)
    const int br = blockIdx.x * BM;
    const int bc = blockIdx.y * BN;
    const int gid = lane >> 2;           // 0..7
    const int qid = lane & 3;            // 0..3

    float acc[4][4][4];
#pragma unroll
    for (int mt = 0; mt < 4; mt++)
#pragma unroll
        for (int nt = 0; nt < 4; nt++)
#pragma unroll
            for (int j = 0; j < 4; j++) acc[mt][nt][j] = 0.f;

    // ldmatrix per-thread source coordinates
    const int aRow = ((lane >> 3) & 1) * 8 + (lane & 7);  // within 16-row A tile
    const int aKof = (lane >> 4) * 8;                     // 0 or 8
    const int bK   = lane & 15;                           // 0..15 (k within 16-k step)

    const int ktiles = (K + BK - 1) / BK;
    for (int kt = 0; kt < ktiles; kt++) {
        const int k0 = kt * BK;
        // ---- load + split A tile: 128 rows x 32 k (fp32 -> 2x bf16) ----
#pragma unroll
        for (int it = 0; it < 4; it++) {
            int f = it * 256 + tid;
            int row = f >> 3, kq = (f & 7) * 4;
            float4 v = make_float4(0.f, 0.f, 0.f, 0.f);
            int gr = br + row;
            if (gr < M && (k0 + kq) < K)
                v = *reinterpret_cast<const float4*>(&A[(size_t)gr * K + k0 + kq]);
            __nv_bfloat16 h0, h1, h2, h3, l0, l1, l2, l3;
            split_bf16(v.x, h0, l0); split_bf16(v.y, h1, l1);
            split_bf16(v.z, h2, l2); split_bf16(v.w, h3, l3);
            *reinterpret_cast<__nv_bfloat162*>(&As1[row][kq])     = __nv_bfloat162(h0, h1);
            *reinterpret_cast<__nv_bfloat162*>(&As1[row][kq + 2]) = __nv_bfloat162(h2, h3);
            *reinterpret_cast<__nv_bfloat162*>(&As2[row][kq])     = __nv_bfloat162(l0, l1);
            *reinterpret_cast<__nv_bfloat162*>(&As2[row][kq + 2]) = __nv_bfloat162(l2, l3);
        }
        // ---- load + split B tile: 32 k x 128 n ----
#pragma unroll
        for (int it = 0; it < 4; it++) {
            int f = it * 256 + tid;
            int krow = f >> 5, n4 = (f & 31) * 4;
            float4 v = make_float4(0.f, 0.f, 0.f, 0.f);
            if ((k0 + krow) < K)
                v = *reinterpret_cast<const float4*>(&Bw[(size_t)(k0 + krow) * N + bc + n4]);
            __nv_bfloat16 h0, h1, h2, h3, l0, l1, l2, l3;
            split_bf16(v.x, h0, l0); split_bf16(v.y, h1, l1);
            split_bf16(v.z, h2, l2); split_bf16(v.w, h3, l3);
            *reinterpret_cast<__nv_bfloat162*>(&Bs1[krow][n4])     = __nv_bfloat162(h0, h1);
            *reinterpret_cast<__nv_bfloat162*>(&Bs1[krow][n4 + 2]) = __nv_bfloat162(h2, h3);
            *reinterpret_cast<__nv_bfloat162*>(&Bs2[krow][n4])     = __nv_bfloat162(l0, l1);
            *reinterpret_cast<__nv_bfloat162*>(&Bs2[krow][n4 + 2]) = __nv_bfloat162(l2, l3);
        }
        __syncthreads();

#pragma unroll
        for (int ks = 0; ks < 2; ks++) {
            const int kk = ks * 16;
            // B fragments for all 4 n-tiles (hi & lo)
            uint32_t bb[4][2], bs[4][2];
#pragma unroll
            for (int nt = 0; nt < 4; nt++) {
                const int n0 = wn * 32 + nt * 8;
                ldm_x2t(bb[nt], &Bs1[kk + bK][n0]);
                ldm_x2t(bs[nt], &Bs2[kk + bK][n0]);
            }
            // per m-tile: load a-frags, 3-term MMAs
#pragma unroll
            for (int mt = 0; mt < 4; mt++) {
                const int r0 = wm * 64 + mt * 16 + aRow;
                uint32_t ah[4], al[4];
                ldm_x4(ah, &As1[r0][kk + aKof]);
                ldm_x4(al, &As2[r0][kk + aKof]);
#pragma unroll
                for (int nt = 0; nt < 4; nt++) {
                    mma_bf16(acc[mt][nt], al, bb[nt]);   // lo·hi
                    mma_bf16(acc[mt][nt], ah, bs[nt]);   // hi·lo
                    mma_bf16(acc[mt][nt], ah, bb[nt]);   // hi·hi (largest last)
                }
            }
        }
        __syncthreads();
    }

    if (SCATTER) {
        // fused message-passing epilogue: no C store, gather x[src], atomic to x1[dst]
        const int cbase = bc + wn * 32 + qid * 2;
#pragma unroll
        for (int mt = 0; mt < 4; mt++) {
#pragma unroll
            for (int half = 0; half < 2; half++) {
                int r = br + wm * 64 + mt * 16 + gid + half * 8;
                if (r >= M) continue;
                int e = r / NGg;
                int k = r - e * NGg;
                int s = eidx[e], d = eidx[Ee + e];
                const float* xrow = &Xsrc[((size_t)(s * NGg + k)) * Hh];
                float* orow = &X1[((size_t)(d * NGg + k)) * Hh];
#pragma unroll
                for (int nt = 0; nt < 4; nt++) {
                    int c = cbase + nt * 8;
                    float2 xv = *reinterpret_cast<const float2*>(&xrow[c]);
                    atomicAdd(&orow[c],     acc[mt][nt][half * 2 + 0] * xv.x);
                    atomicAdd(&orow[c + 1], acc[mt][nt][half * 2 + 1] * xv.y);
                }
            }
        }
        return;
    }

    // epilogue: frag c0,c1 -> (row r0, cols c,c+1); c2,c3 -> (row r0+8)
#pragma unroll
    for (int nt = 0; nt < 4; nt++) {
        const int c = bc + wn * 32 + nt * 8 + qid * 2;
        float b0 = 0.f, b1 = 0.f;
        if (bias) { b0 = bias[c]; b1 = bias[c + 1]; }
#pragma unroll
        for (int mt = 0; mt < 4; mt++) {
            int r0 = br + wm * 64 + mt * 16 + gid;
#pragma unroll
            for (int half = 0; half < 2; half++) {
                int r = r0 + half * 8;
                if (r >= M) continue;
                float v0 = acc[mt][nt][half * 2 + 0] + b0;
                float v1 = acc[mt][nt][half * 2 + 1] + b1;
                if (GELU) { v0 = gelu_f(v0); v1 = gelu_f(v1); }
                float2* p = reinterpret_cast<float2*>(&C[(size_t)r * N + c]);
                if (ACCUM) {
                    float2 o = *p;
                    o.x += v0; o.y += v1;
                    *p = o;
                } else {
                    *p = make_float2(v0, v1);
                }
            }
        }
    }
}

// ---------------- host launch ----------------------------------------------------
static void launch_gemm(const float* A, const float* W, const float* bias, float* C,
                        int M, int N, int K, bool gelu_act, bool accum) {
    dim3 grid((M + BM - 1) / BM, N / BN);
    if (gelu_act)
        gemm_bf16x3<true, false, false><<<grid, 256>>>(A, W, bias, C, M, N, K,
                                                       nullptr, nullptr, nullptr);
    else if (accum)
        gemm_bf16x3<false, true, false><<<grid, 256>>>(A, W, bias, C, M, N, K,
                                                       nullptr, nullptr, nullptr);
    else
        gemm_bf16x3<false, false, false><<<grid, 256>>>(A, W, bias, C, M, N, K,
                                                        nullptr, nullptr, nullptr);
}

static void launch_gemm_scatter(const float* A, const float* W,
                                int M, int N, int K,
                                const int* eidx, const float* Xsrc, float* X1) {
    dim3 grid((M + BM - 1) / BM, N / BN);
    gemm_bf16x3<false, false, true><<<grid, 256>>>(A, W, nullptr, nullptr, M, N, K,
                                                   eidx, Xsrc, X1);
}

extern "C" void kernel_launch(void* const* d_in, const int* in_sizes, int n_in,
                              void* d_out, int out_size) {
    const float* pos      = (const float*)d_in[0];
    const float* vel      = (const float*)d_in[1];
    const float* charges  = (const float*)d_in[2];
    const int*   batch    = (const int*)d_in[3];
    const int*   eidx     = (const int*)d_in[4];
    const float* grid0    = (const float*)d_in[5];
    const float* R        = (const float*)d_in[6];
    const float* W_basis1 = (const float*)d_in[7];
    const float* b_basis1 = (const float*)d_in[8];
    const float* W_basis2 = (const float*)d_in[9];
    const float* b_basis2 = (const float*)d_in[10];
    const float* W_fbasis1 = (const float*)d_in[11];
    const float* b_fbasis1 = (const float*)d_in[12];
    const float* W_fbasis2 = (const float*)d_in[13];
    const float* b_fbasis2 = (const float*)d_in[14];
    const float* W_embed  = (const float*)d_in[15];
    const float* W_conv   = (const float*)d_in[16];
    const float* W_fiber  = (const float*)d_in[17];
    const float* b_conv   = (const float*)d_in[18];
    const float* ln_gamma = (const float*)d_in[19];
    const float* ln_beta  = (const float*)d_in[20];
    const float* W_ff1    = (const float*)d_in[21];
    const float* b_ff1    = (const float*)d_in[22];
    const float* W_ff2    = (const float*)d_in[23];
    const float* b_ff2    = (const float*)d_in[24];
    const float* W_ro1    = (const float*)d_in[25];
    const float* b_ro1    = (const float*)d_in[26];
    const float* W_ro2    = (const float*)d_in[27];
    const float* b_ro2    = (const float*)d_in[28];
    float* out = (float*)d_out;

    float *bufA, *basis, *x, *x1, *x2, *ffh, *eip, *fip, *fh1, *fbasis, *fk, *gsum;
    cudaGetSymbolAddress((void**)&bufA,  g_bufA);
    cudaGetSymbolAddress((void**)&basis, g_basis);
    cudaGetSymbolAddress((void**)&x,     g_x);
    cudaGetSymbolAddress((void**)&x1,    g_x1);
    cudaGetSymbolAddress((void**)&x2,    g_x2);
    cudaGetSymbolAddress((void**)&ffh,   g_ffh);
    cudaGetSymbolAddress((void**)&eip,   g_eipoly);
    cudaGetSymbolAddress((void**)&fip,   g_fipoly);
    cudaGetSymbolAddress((void**)&fh1,   g_fh1);
    cudaGetSymbolAddress((void**)&fbasis,g_fbasis);
    cudaGetSymbolAddress((void**)&fk,    g_fk);
    cudaGetSymbolAddress((void**)&gsum,  g_gsum);

    // graph statistics + rotated grids
    k_zero<<<(Bb * 4 + 255) / 256, 256>>>(gsum, Bb * 4);
    k_gsum<<<(Nn + 255) / 256, 256>>>(pos, batch);
    k_grid_node<<<(Nn * NGg + 255) / 256, 256>>>(batch, grid0, R);

    // edge basis MLP: 600k rows
    k_eipoly<<<(EROWS + 255) / 256, 256>>>(pos, charges, eidx);
    launch_gemm(eip,  W_basis1, b_basis1, bufA,  EROWS, Hh, 12, true, false);
    launch_gemm(bufA, W_basis2, b_basis2, basis, EROWS, BDd, Hh, true, false);

    // fiber basis MLP: 144 rows
    k_fipoly<<<1, 256>>>(grid0);
    k_small_gemm<<<(NGg * NGg * Hh + 255) / 256, 256>>>(fip, W_fbasis1, b_fbasis1, fh1,
                                                        NGg * NGg, Hh, 2, 1);
    k_small_gemm<<<(NGg * NGg * BDd + 255) / 256, 256>>>(fh1, W_fbasis2, b_fbasis2, fbasis,
                                                         NGg * NGg, BDd, Hh, 1);

    // node embedding
    k_embed<<<NROWS, Hh>>>(pos, vel, charges, batch, W_embed);

    for (int l = 0; l < Ll; l++) {
        // fused: kern = basis @ W_conv[l]; x1 += scatter(x[src] * kern -> dst)
        k_zero<<<(NROWS * Hh + 255) / 256, 256>>>(x1, NROWS * Hh);
        launch_gemm_scatter(basis, W_conv + (size_t)l * BDd * Hh, EROWS, Hh, BDd,
                            eidx, x, x1);
        // fk = fiber_basis @ W_fiber[l]
        k_small_gemm<<<(NGg * NGg * Hh + 255) / 256, 256>>>(
            fbasis, W_fiber + (size_t)l * BDd * Hh, nullptr, fk, NGg * NGg, Hh, BDd, 0);
        // x2 = einsum/NG + b_conv, LayerNorm -> g_x2
        k_fiber_ln<<<NROWS, Hh>>>(b_conv + l * Hh, ln_gamma + l * Hh, ln_beta + l * Hh);
        // FF: x += W_ff2 @ gelu(W_ff1 @ h)
        launch_gemm(x2, W_ff1 + (size_t)l * Hh * 4 * Hh, b_ff1 + l * 4 * Hh, ffh,
                    NROWS, 4 * Hh, Hh, true, false);
        launch_gemm(ffh, W_ff2 + (size_t)l * 4 * Hh * Hh, b_ff2 + l * Hh, x,
                    NROWS, Hh, 4 * Hh, false, true);
    }

    // readout
    launch_gemm(x, W_ro1, b_ro1, ffh, NROWS, Hh, Hh, true, false);
    k_output<<<Nn, Hh>>>(W_ro2, b_ro2, out);
}

// round 8
// speedup vs baseline: 1.4462x; 1.4462x over previous
#include <cuda_runtime.h>
#include <cuda_bf16.h>
#include <math.h>
#include <stdint.h>

// Problem dims (fixed by the dataset)
constexpr int Nn  = 4000;
constexpr int Ee  = 50000;
constexpr int NGg = 12;
constexpr int Hh  = 128;
constexpr int BDd = 128;
constexpr int Ll  = 2;
constexpr int Bb  = 100;

constexpr int EROWS = Ee * NGg;     // 600000
constexpr int NROWS = Nn * NGg;     // 48000

// ---------------- scratch (device globals; no cudaMalloc allowed) -------------
__device__ __align__(16) float g_grid_node[Nn * NGg * 3];
__device__ __align__(16) float g_eipoly[EROWS * 12];
__device__ __align__(16) float g_bufA[EROWS * BDd];      // h1, then kern
__device__ __align__(16) float g_basis[EROWS * BDd];
__device__ __align__(16) float g_x  [NROWS * Hh];
__device__ __align__(16) float g_x2 [NROWS * Hh];
__device__ __align__(16) float g_ffh[NROWS * 4 * Hh];
__device__ __align__(16) float g_fipoly[NGg * NGg * 2];
__device__ __align__(16) float g_fh1   [NGg * NGg * Hh];
__device__ __align__(16) float g_fbasis[NGg * NGg * BDd];
__device__ __align__(16) float g_fk    [NGg * NGg * Hh];
__device__ float g_gsum[Bb * 4];   // per-graph: sum_x, sum_y, sum_z, count
// CSR by destination
__device__ int g_deg[Nn];
__device__ int g_off[Nn + 1];
__device__ int g_cur[Nn];
__device__ int g_csr[Ee];

__device__ __forceinline__ float gelu_f(float x) {
    return 0.5f * x * (1.0f + erff(x * 0.70710678118654752f));
}

// ---------------- tiny kernels -------------------------------------------------
__global__ void k_zero(float* p, int n) {
    int i = blockIdx.x * blockDim.x + threadIdx.x;
    if (i < n) p[i] = 0.f;
}

__global__ void k_zero_int(int* p, int n) {
    int i = blockIdx.x * blockDim.x + threadIdx.x;
    if (i < n) p[i] = 0;
}

__global__ void k_gsum(const float* __restrict__ pos, const int* __restrict__ batch) {
    int n = blockIdx.x * blockDim.x + threadIdx.x;
    if (n >= Nn) return;
    int b = batch[n];
    atomicAdd(&g_gsum[b * 4 + 0], pos[n * 3 + 0]);
    atomicAdd(&g_gsum[b * 4 + 1], pos[n * 3 + 1]);
    atomicAdd(&g_gsum[b * 4 + 2], pos[n * 3 + 2]);
    atomicAdd(&g_gsum[b * 4 + 3], 1.f);
}

__global__ void k_grid_node(const int* __restrict__ batch,
                            const float* __restrict__ grid0,
                            const float* __restrict__ R) {
    int idx = blockIdx.x * blockDim.x + threadIdx.x;  // n*NG + k
    if (idx >= Nn * NGg) return;
    int n = idx / NGg, k = idx % NGg;
    const float* Rb = R + batch[n] * 9;
    float gx = grid0[k * 3 + 0], gy = grid0[k * 3 + 1], gz = grid0[k * 3 + 2];
    float* o = g_grid_node + idx * 3;
    o[0] = Rb[0] * gx + Rb[1] * gy + Rb[2] * gz;
    o[1] = Rb[3] * gx + Rb[4] * gy + Rb[5] * gz;
    o[2] = Rb[6] * gx + Rb[7] * gy + Rb[8] * gz;
}

__global__ void k_eipoly(const float* __restrict__ pos,
                         const float* __restrict__ charges,
                         const int* __restrict__ eidx) {
    int idx = blockIdx.x * blockDim.x + threadIdx.x;  // e*NG + k
    if (idx >= EROWS) return;
    int e = idx / NGg, k = idx % NGg;
    int s = eidx[e], d = eidx[Ee + e];
    float rx = pos[s * 3 + 0] - pos[d * 3 + 0];
    float ry = pos[s * 3 + 1] - pos[d * 3 + 1];
    float rz = pos[s * 3 + 2] - pos[d * 3 + 2];
    const float* g = g_grid_node + (s * NGg + k) * 3;
    float inv1 = rx * g[0] + ry * g[1] + rz * g[2];
    float vx = rx - inv1 * g[0], vy = ry - inv1 * g[1], vz = rz - inv1 * g[2];
    float inv2 = sqrtf(vx * vx + vy * vy + vz * vz);
    float cp = charges[s] * charges[d];
    float e0 = inv1, e1 = inv2, e2 = cp;
    float* o = g_eipoly + (size_t)idx * 12;
    o[0] = e0;  o[1] = e1;  o[2] = e2;
    o[3] = e0 * e0; o[4]  = e0 * e1; o[5]  = e0 * e2;
    o[6] = e1 * e0; o[7]  = e1 * e1; o[8]  = e1 * e2;
    o[9] = e2 * e0; o[10] = e2 * e1; o[11] = e2 * e2;
}

__global__ void k_fipoly(const float* __restrict__ grid0) {
    int idx = threadIdx.x;
    if (idx >= NGg * NGg) return;
    int p = idx / NGg, o = idx % NGg;
    float fi = grid0[p * 3 + 0] * grid0[o * 3 + 0] +
               grid0[p * 3 + 1] * grid0[o * 3 + 1] +
               grid0[p * 3 + 2] * grid0[o * 3 + 2];
    g_fipoly[idx * 2 + 0] = fi;
    g_fipoly[idx * 2 + 1] = fi * fi;
}

// naive GEMM for tiny fiber matrices (M=144) — fp32, negligible time
__global__ void k_small_gemm(const float* __restrict__ A, const float* __restrict__ W,
                             const float* __restrict__ bias, float* __restrict__ C,
                             int M, int N, int K, int act) {
    int idx = blockIdx.x * blockDim.x + threadIdx.x;
    if (idx >= M * N) return;
    int r = idx / N, c = idx % N;
    float acc = bias ? bias[c] : 0.f;
    for (int k = 0; k < K; k++) acc = fmaf(A[r * K + k], W[k * N + c], acc);
    C[idx] = act ? gelu_f(acc) : acc;
}

__global__ void k_embed(const float* __restrict__ pos, const float* __restrict__ vel,
                        const float* __restrict__ charges, const int* __restrict__ batch,
                        const float* __restrict__ We) {
    int nk = blockIdx.x;           // n*NG + k
    int h = threadIdx.x;           // 0..127
    int n = nk / NGg;
    const float* g = g_grid_node + nk * 3;
    float vx = vel[n * 3 + 0], vy = vel[n * 3 + 1], vz = vel[n * 3 + 2];
    int b = batch[n];
    float cnt = fmaxf(g_gsum[b * 4 + 3], 1.f);
    float rpx = pos[n * 3 + 0] - g_gsum[b * 4 + 0] / cnt;
    float rpy = pos[n * 3 + 1] - g_gsum[b * 4 + 1] / cnt;
    float rpz = pos[n * 3 + 2] - g_gsum[b * 4 + 2] / cnt;
    float f0 = vx * g[0] + vy * g[1] + vz * g[2];
    float f1 = rpx * g[0] + rpy * g[1] + rpz * g[2];
    float f2 = charges[n];
    float f3 = sqrtf(vx * vx + vy * vy + vz * vz);
    g_x[(size_t)nk * Hh + h] =
        f0 * We[h] + f1 * We[Hh + h] + f2 * We[2 * Hh + h] + f3 * We[3 * Hh + h];
}

// ---------------- CSR build (by destination) ------------------------------------
__global__ void k_count(const int* __restrict__ eidx) {
    int e = blockIdx.x * blockDim.x + threadIdx.x;
    if (e >= Ee) return;
    atomicAdd(&g_deg[eidx[Ee + e]], 1);
}

// single-block exclusive scan of g_deg[0..Nn) -> g_off
__global__ void k_scan() {
    __shared__ int sh[1024];
    int tid = threadIdx.x;
    int base = tid * 4;
    int v[4];
    int s0 = 0;
#pragma unroll
    for (int i = 0; i < 4; i++) {
        int idx = base + i;
        v[i] = (idx < Nn) ? g_deg[idx] : 0;
        s0 += v[i];
    }
    sh[tid] = s0;
    __syncthreads();
    for (int off = 1; off < 1024; off <<= 1) {
        int t = (tid >= off) ? sh[tid - off] : 0;
        __syncthreads();
        sh[tid] += t;
        __syncthreads();
    }
    int ex = sh[tid] - s0;   // exclusive prefix for this thread's chunk
#pragma unroll
    for (int i = 0; i < 4; i++) {
        int idx = base + i;
        if (idx < Nn) { g_off[idx] = ex; ex += v[i]; }
    }
    if (tid == 1023) g_off[Nn] = sh[1023];
}

__global__ void k_fill(const int* __restrict__ eidx) {
    int e = blockIdx.x * blockDim.x + threadIdx.x;
    if (e >= Ee) return;
    int d = eidx[Ee + e];
    int pos = g_off[d] + atomicAdd(&g_cur[d], 1);
    g_csr[pos] = e;
}

// ---------------- fused gather + fiber contraction + LayerNorm ------------------
// block = node n, thread = channel c.
// acc[o] = sum over incoming edges e of kern[e,o,c] * x[src(e),o,c]   (o = 0..11)
// x2[n,p,c] = LN_c( (1/12) * sum_o acc[o] * fk[p,o,c] + b_conv[c] )
__global__ void __launch_bounds__(128) k_gather_fiber_ln(
    const int* __restrict__ eidx,
    const float* __restrict__ bconv, const float* __restrict__ gamma,
    const float* __restrict__ beta) {
    int n = blockIdx.x;
    int c = threadIdx.x;
    float acc[NGg];
#pragma unroll
    for (int o = 0; o < NGg; o++) acc[o] = 0.f;

    const int beg = g_off[n], end = g_off[n + 1];
    for (int j = beg; j < end; j++) {
        int e = g_csr[j];
        int s = eidx[e];
        const float* kr = &g_bufA[(size_t)e * NGg * Hh + c];
        const float* xr = &g_x[(size_t)s * NGg * Hh + c];
#pragma unroll
        for (int o = 0; o < NGg; o++)
            acc[o] = fmaf(kr[o * Hh], xr[o * Hh], acc[o]);
    }

    __shared__ float red[4];
    for (int p = 0; p < NGg; p++) {
        float v = 0.f;
        const float* fkp = &g_fk[(size_t)p * NGg * Hh + c];
#pragma unroll
        for (int o = 0; o < NGg; o++)
            v = fmaf(acc[o], fkp[o * Hh], v);
        v = v * (1.0f / NGg) + bconv[c];

        float s = v;
#pragma unroll
        for (int off = 16; off > 0; off >>= 1) s += __shfl_down_sync(0xffffffffu, s, off);
        if ((c & 31) == 0) red[c >> 5] = s;
        __syncthreads();
        float mean = (red[0] + red[1] + red[2] + red[3]) * (1.f / Hh);
        __syncthreads();
        float dd = v - mean;
        s = dd * dd;
#pragma unroll
        for (int off = 16; off > 0; off >>= 1) s += __shfl_down_sync(0xffffffffu, s, off);
        if ((c & 31) == 0) red[c >> 5] = s;
        __syncthreads();
        float var = (red[0] + red[1] + red[2] + red[3]) * (1.f / Hh);
        g_x2[((size_t)n * NGg + p) * Hh + c] = dd * rsqrtf(var + 1e-5f) * gamma[c] + beta[c];
        __syncthreads();
    }
}

// out[n,d] = (1/NG) sum_k grid_node[n,k,d] * (t[n,k,:]·W_ro2 + b_ro2)
__global__ void k_output(const float* __restrict__ Wro2, const float* __restrict__ bro2,
                         float* __restrict__ out) {
    int n = blockIdx.x;
    int h = threadIdx.x;
    __shared__ float red[4];
    __shared__ float ybc;
    float a0 = 0.f, a1 = 0.f, a2 = 0.f;
    for (int k = 0; k < NGg; k++) {
        float s = g_ffh[((size_t)(n * NGg + k)) * Hh + h] * Wro2[h];
#pragma unroll
        for (int off = 16; off > 0; off >>= 1) s += __shfl_down_sync(0xffffffffu, s, off);
        if ((h & 31) == 0) red[h >> 5] = s;
        __syncthreads();
        if (h == 0) ybc = red[0] + red[1] + red[2] + red[3] + bro2[0];
        __syncthreads();
        float y = ybc;
        a0 += g_grid_node[(n * NGg + k) * 3 + 0] * y;
        a1 += g_grid_node[(n * NGg + k) * 3 + 1] * y;
        a2 += g_grid_node[(n * NGg + k) * 3 + 2] * y;
        __syncthreads();
    }
    if (h == 0) {
        out[n * 3 + 0] = a0 * (1.f / NGg);
        out[n * 3 + 1] = a1 * (1.f / NGg);
        out[n * 3 + 2] = a2 * (1.f / NGg);
    }
}

// ---------------- bf16x3 tensor-core GEMM (≈fp32 accuracy) ---------------------
// C = [act](A @ Bw + bias) [+= if ACCUM]
// A: MxK row-major (K % 4 == 0), Bw: KxN row-major, N % 128 == 0.
// Block 128x128, BK=32, 8 warps, warp tile 64x32 via mma.m16n8k16.bf16.
// Split x = hi + lo (hi = bf16(x), lo = bf16(x - hi)); D += hh + hl + lh.
constexpr int BM = 128, BN = 128, BK = 32;
constexpr int ASTRIDE = BK + 8;      // 40 bf16 per row -> conflict-free ldmatrix
constexpr int BSTRIDE = BN + 8;      // 136 bf16 per row -> conflict-free ldmatrix.trans

__device__ __forceinline__ void mma_bf16(float* d, const uint32_t* a, const uint32_t* b) {
    asm volatile(
        "mma.sync.aligned.m16n8k16.row.col.f32.bf16.bf16.f32 "
        "{%0,%1,%2,%3}, {%4,%5,%6,%7}, {%8,%9}, {%0,%1,%2,%3};\n"
        : "+f"(d[0]), "+f"(d[1]), "+f"(d[2]), "+f"(d[3])
        : "r"(a[0]), "r"(a[1]), "r"(a[2]), "r"(a[3]), "r"(b[0]), "r"(b[1]));
}

__device__ __forceinline__ void ldm_x4(uint32_t* r, const __nv_bfloat16* p) {
    uint32_t addr = (uint32_t)__cvta_generic_to_shared(p);
    asm volatile("ldmatrix.sync.aligned.m8n8.x4.shared.b16 {%0,%1,%2,%3}, [%4];"
                 : "=r"(r[0]), "=r"(r[1]), "=r"(r[2]), "=r"(r[3]) : "r"(addr));
}

__device__ __forceinline__ void ldm_x2t(uint32_t* r, const __nv_bfloat16* p) {
    uint32_t addr = (uint32_t)__cvta_generic_to_shared(p);
    asm volatile("ldmatrix.sync.aligned.m8n8.x2.trans.shared.b16 {%0,%1}, [%2];"
                 : "=r"(r[0]), "=r"(r[1]) : "r"(addr));
}

__device__ __forceinline__ void split_bf16(float v, __nv_bfloat16& hi, __nv_bfloat16& lo) {
    hi = __float2bfloat16_rn(v);
    lo = __float2bfloat16_rn(v - __bfloat162float(hi));
}

template <bool GELU, bool ACCUM>
__global__ void __launch_bounds__(256, 2) gemm_bf16x3(
    const float* __restrict__ A, const float* __restrict__ Bw,
    const float* __restrict__ bias, float* __restrict__ C,
    int M, int N, int K) {
    __shared__ __nv_bfloat16 As1[BM][ASTRIDE];   // A hi
    __shared__ __nv_bfloat16 As2[BM][ASTRIDE];   // A lo
    __shared__ __nv_bfloat16 Bs1[BK][BSTRIDE];   // B hi (layout [k][n])
    __shared__ __nv_bfloat16 Bs2[BK][BSTRIDE];   // B lo

    const int tid  = threadIdx.x;
    const int lane = tid & 31;
    const int warp = tid >> 5;
    const int wm = warp & 1;             // 2 warps along M (64 rows each)
    const int wn = warp >> 1;            // 4 warps along N (32 cols each)
    const int br = blockIdx.x * BM;
    const int bc = blockIdx.y * BN;
    const int gid = lane >> 2;           // 0..7
    const int qid = lane & 3;            // 0..3

    float acc[4][4][4];
#pragma unroll
    for (int mt = 0; mt < 4; mt++)
#pragma unroll
        for (int nt = 0; nt < 4; nt++)
#pragma unroll
            for (int j = 0; j < 4; j++) acc[mt][nt][j] = 0.f;

    // ldmatrix per-thread source coordinates
    const int aRow = ((lane >> 3) & 1) * 8 + (lane & 7);  // within 16-row A tile
    const int aKof = (lane >> 4) * 8;                     // 0 or 8
    const int bK   = lane & 15;                           // 0..15 (k within 16-k step)

    const int ktiles = (K + BK - 1) / BK;
    for (int kt = 0; kt < ktiles; kt++) {
        const int k0 = kt * BK;
        // ---- load + split A tile: 128 rows x 32 k (fp32 -> 2x bf16) ----
#pragma unroll
        for (int it = 0; it < 4; it++) {
            int f = it * 256 + tid;
            int row = f >> 3, kq = (f & 7) * 4;
            float4 v = make_float4(0.f, 0.f, 0.f, 0.f);
            int gr = br + row;
            if (gr < M && (k0 + kq) < K)
                v = *reinterpret_cast<const float4*>(&A[(size_t)gr * K + k0 + kq]);
            __nv_bfloat16 h0, h1, h2, h3, l0, l1, l2, l3;
            split_bf16(v.x, h0, l0); split_bf16(v.y, h1, l1);
            split_bf16(v.z, h2, l2); split_bf16(v.w, h3, l3);
            *reinterpret_cast<__nv_bfloat162*>(&As1[row][kq])     = __nv_bfloat162(h0, h1);
            *reinterpret_cast<__nv_bfloat162*>(&As1[row][kq + 2]) = __nv_bfloat162(h2, h3);
            *reinterpret_cast<__nv_bfloat162*>(&As2[row][kq])     = __nv_bfloat162(l0, l1);
            *reinterpret_cast<__nv_bfloat162*>(&As2[row][kq + 2]) = __nv_bfloat162(l2, l3);
        }
        // ---- load + split B tile: 32 k x 128 n ----
#pragma unroll
        for (int it = 0; it < 4; it++) {
            int f = it * 256 + tid;
            int krow = f >> 5, n4 = (f & 31) * 4;
            float4 v = make_float4(0.f, 0.f, 0.f, 0.f);
            if ((k0 + krow) < K)
                v = *reinterpret_cast<const float4*>(&Bw[(size_t)(k0 + krow) * N + bc + n4]);
            __nv_bfloat16 h0, h1, h2, h3, l0, l1, l2, l3;
            split_bf16(v.x, h0, l0); split_bf16(v.y, h1, l1);
            split_bf16(v.z, h2, l2); split_bf16(v.w, h3, l3);
            *reinterpret_cast<__nv_bfloat162*>(&Bs1[krow][n4])     = __nv_bfloat162(h0, h1);
            *reinterpret_cast<__nv_bfloat162*>(&Bs1[krow][n4 + 2]) = __nv_bfloat162(h2, h3);
            *reinterpret_cast<__nv_bfloat162*>(&Bs2[krow][n4])     = __nv_bfloat162(l0, l1);
            *reinterpret_cast<__nv_bfloat162*>(&Bs2[krow][n4 + 2]) = __nv_bfloat162(l2, l3);
        }
        __syncthreads();

#pragma unroll
        for (int ks = 0; ks < 2; ks++) {
            const int kk = ks * 16;
            // B fragments for all 4 n-tiles (hi & lo)
            uint32_t bb[4][2], bs[4][2];
#pragma unroll
            for (int nt = 0; nt < 4; nt++) {
                const int n0 = wn * 32 + nt * 8;
                ldm_x2t(bb[nt], &Bs1[kk + bK][n0]);
                ldm_x2t(bs[nt], &Bs2[kk + bK][n0]);
            }
            // per m-tile: load a-frags, 3-term MMAs
#pragma unroll
            for (int mt = 0; mt < 4; mt++) {
                const int r0 = wm * 64 + mt * 16 + aRow;
                uint32_t ah[4], al[4];
                ldm_x4(ah, &As1[r0][kk + aKof]);
                ldm_x4(al, &As2[r0][kk + aKof]);
#pragma unroll
                for (int nt = 0; nt < 4; nt++) {
                    mma_bf16(acc[mt][nt], al, bb[nt]);   // lo·hi
                    mma_bf16(acc[mt][nt], ah, bs[nt]);   // hi·lo
                    mma_bf16(acc[mt][nt], ah, bb[nt]);   // hi·hi (largest last)
                }
            }
        }
        __syncthreads();
    }

    // epilogue: frag c0,c1 -> (row r0, cols c,c+1); c2,c3 -> (row r0+8)
#pragma unroll
    for (int nt = 0; nt < 4; nt++) {
        const int c = bc + wn * 32 + nt * 8 + qid * 2;
        float b0 = 0.f, b1 = 0.f;
        if (bias) { b0 = bias[c]; b1 = bias[c + 1]; }
#pragma unroll
        for (int mt = 0; mt < 4; mt++) {
            int r0 = br + wm * 64 + mt * 16 + gid;
#pragma unroll
            for (int half = 0; half < 2; half++) {
                int r = r0 + half * 8;
                if (r >= M) continue;
                float v0 = acc[mt][nt][half * 2 + 0] + b0;
                float v1 = acc[mt][nt][half * 2 + 1] + b1;
                if (GELU) { v0 = gelu_f(v0); v1 = gelu_f(v1); }
                float2* p = reinterpret_cast<float2*>(&C[(size_t)r * N + c]);
                if (ACCUM) {
                    float2 o = *p;
                    o.x += v0; o.y += v1;
                    *p = o;
                } else {
                    *p = make_float2(v0, v1);
                }
            }
        }
    }
}

// ---------------- host launch ----------------------------------------------------
static void launch_gemm(const float* A, const float* W, const float* bias, float* C,
                        int M, int N, int K, bool gelu_act, bool accum) {
    dim3 grid((M + BM - 1) / BM, N / BN);
    if (gelu_act)   gemm_bf16x3<true, false><<<grid, 256>>>(A, W, bias, C, M, N, K);
    else if (accum) gemm_bf16x3<false, true><<<grid, 256>>>(A, W, bias, C, M, N, K);
    else            gemm_bf16x3<false, false><<<grid, 256>>>(A, W, bias, C, M, N, K);
}

extern "C" void kernel_launch(void* const* d_in, const int* in_sizes, int n_in,
                              void* d_out, int out_size) {
    const float* pos      = (const float*)d_in[0];
    const float* vel      = (const float*)d_in[1];
    const float* charges  = (const float*)d_in[2];
    const int*   batch    = (const int*)d_in[3];
    const int*   eidx     = (const int*)d_in[4];
    const float* grid0    = (const float*)d_in[5];
    const float* R        = (const float*)d_in[6];
    const float* W_basis1 = (const float*)d_in[7];
    const float* b_basis1 = (const float*)d_in[8];
    const float* W_basis2 = (const float*)d_in[9];
    const float* b_basis2 = (const float*)d_in[10];
    const float* W_fbasis1 = (const float*)d_in[11];
    const float* b_fbasis1 = (const float*)d_in[12];
    const float* W_fbasis2 = (const float*)d_in[13];
    const float* b_fbasis2 = (const float*)d_in[14];
    const float* W_embed  = (const float*)d_in[15];
    const float* W_conv   = (const float*)d_in[16];
    const float* W_fiber  = (const float*)d_in[17];
    const float* b_conv   = (const float*)d_in[18];
    const float* ln_gamma = (const float*)d_in[19];
    const float* ln_beta  = (const float*)d_in[20];
    const float* W_ff1    = (const float*)d_in[21];
    const float* b_ff1    = (const float*)d_in[22];
    const float* W_ff2    = (const float*)d_in[23];
    const float* b_ff2    = (const float*)d_in[24];
    const float* W_ro1    = (const float*)d_in[25];
    const float* b_ro1    = (const float*)d_in[26];
    const float* W_ro2    = (const float*)d_in[27];
    const float* b_ro2    = (const float*)d_in[28];
    float* out = (float*)d_out;

    float *bufA, *basis, *x, *x2, *ffh, *eip, *fip, *fh1, *fbasis, *fk, *gsum;
    int *deg, *cur;
    cudaGetSymbolAddress((void**)&bufA,  g_bufA);
    cudaGetSymbolAddress((void**)&basis, g_basis);
    cudaGetSymbolAddress((void**)&x,     g_x);
    cudaGetSymbolAddress((void**)&x2,    g_x2);
    cudaGetSymbolAddress((void**)&ffh,   g_ffh);
    cudaGetSymbolAddress((void**)&eip,   g_eipoly);
    cudaGetSymbolAddress((void**)&fip,   g_fipoly);
    cudaGetSymbolAddress((void**)&fh1,   g_fh1);
    cudaGetSymbolAddress((void**)&fbasis,g_fbasis);
    cudaGetSymbolAddress((void**)&fk,    g_fk);
    cudaGetSymbolAddress((void**)&gsum,  g_gsum);
    cudaGetSymbolAddress((void**)&deg,   g_deg);
    cudaGetSymbolAddress((void**)&cur,   g_cur);

    // graph statistics + rotated grids
    k_zero<<<(Bb * 4 + 255) / 256, 256>>>(gsum, Bb * 4);
    k_gsum<<<(Nn + 255) / 256, 256>>>(pos, batch);
    k_grid_node<<<(Nn * NGg + 255) / 256, 256>>>(batch, grid0, R);

    // CSR by destination (built once, reused by both layers)
    k_zero_int<<<(Nn + 255) / 256, 256>>>(deg, Nn);
    k_zero_int<<<(Nn + 255) / 256, 256>>>(cur, Nn);
    k_count<<<(Ee + 255) / 256, 256>>>(eidx);
    k_scan<<<1, 1024>>>();
    k_fill<<<(Ee + 255) / 256, 256>>>(eidx);

    // edge basis MLP: 600k rows
    k_eipoly<<<(EROWS + 255) / 256, 256>>>(pos, charges, eidx);
    launch_gemm(eip,  W_basis1, b_basis1, bufA,  EROWS, Hh, 12, true, false);
    launch_gemm(bufA, W_basis2, b_basis2, basis, EROWS, BDd, Hh, true, false);

    // fiber basis MLP: 144 rows
    k_fipoly<<<1, 256>>>(grid0);
    k_small_gemm<<<(NGg * NGg * Hh + 255) / 256, 256>>>(fip, W_fbasis1, b_fbasis1, fh1,
                                                        NGg * NGg, Hh, 2, 1);
    k_small_gemm<<<(NGg * NGg * BDd + 255) / 256, 256>>>(fh1, W_fbasis2, b_fbasis2, fbasis,
                                                         NGg * NGg, BDd, Hh, 1);

    // node embedding
    k_embed<<<NROWS, Hh>>>(pos, vel, charges, batch, W_embed);

    for (int l = 0; l < Ll; l++) {
        // kern = basis @ W_conv[l]  (600k x 128 x 128) -> bufA
        launch_gemm(basis, W_conv + (size_t)l * BDd * Hh, nullptr, bufA, EROWS, Hh, BDd,
                    false, false);
        // fk = fiber_basis @ W_fiber[l]
        k_small_gemm<<<(NGg * NGg * Hh + 255) / 256, 256>>>(
            fbasis, W_fiber + (size_t)l * BDd * Hh, nullptr, fk, NGg * NGg, Hh, BDd, 0);
        // fused: x1 = gather-sum(kern * x[src] -> dst); x2 = LN(fiber(x1)) in one pass
        k_gather_fiber_ln<<<Nn, Hh>>>(eidx, b_conv + l * Hh, ln_gamma + l * Hh,
                                      ln_beta + l * Hh);
        // FF: x += W_ff2 @ gelu(W_ff1 @ h)
        launch_gemm(x2, W_ff1 + (size_t)l * Hh * 4 * Hh, b_ff1 + l * 4 * Hh, ffh,
                    NROWS, 4 * Hh, Hh, true, false);
        launch_gemm(ffh, W_ff2 + (size_t)l * 4 * Hh * Hh, b_ff2 + l * Hh, x,
                    NROWS, Hh, 4 * Hh, false, true);
    }

    // readout
    launch_gemm(x, W_ro1, b_ro1, ffh, NROWS, Hh, Hh, true, false);
    k_output<<<Nn, Hh>>>(W_ro2, b_ro2, out);
}